// round 14
// baseline (speedup 1.0000x reference)
#include <cuda_runtime.h>

#define C    256
#define CH   128
#define HWn  262144
#define HW4  65536
#define SEGS 16
#define SEG_F4 4096   // float4s per (c,seg) chunk
#define EPS  1e-5f

#define TP     32
#define TP4    8
#define TILE_F  (C * TP)       // 8192 floats = 32 KB
#define NTILES  (HWn / TP)     // 8192 tiles
#define NCHUNKS (C * SEGS)     // 4096 phase-A chunks

__device__ float d_partials[NCHUNKS];
__device__ float d_g[C];
__device__ float d_v[C];
__device__ float d_b0;
__device__ int d_ctrA;          // phase-A work counter   (reset at end of kernel)
__device__ int d_ctrB;          // phase-B work counter
__device__ unsigned d_doneA;    // phase-A completion count
__device__ unsigned d_doneB;    // phase-B completion count
__device__ volatile unsigned d_flag;   // scalars-ready flag

__device__ __forceinline__ void k3_prefetch(const float4* __restrict__ x4,
                                            float* buf, int tile, int t) {
    if (tile < NTILES) {
        unsigned dst_base = (unsigned)__cvta_generic_to_shared(buf);
        const int base4 = tile * TP4;
#pragma unroll
        for (int j = 0; j < 8; j++) {
            int i4 = t + j * 256;
            int c = i4 >> 3, p4 = i4 & 7;
            const float4* src = x4 + (size_t)c * HW4 + base4 + p4;
            unsigned dst = dst_base + i4 * 16;
            asm volatile("cp.async.cg.shared.global [%0], [%1], 16;\n" :: "r"(dst), "l"(src));
        }
    }
    asm volatile("cp.async.commit_group;\n");
}

__global__ __launch_bounds__(256, 3)
void psa_fused(const float4* __restrict__ x4, float4* __restrict__ out4, int ncta,
               const float* __restrict__ cv1w, const float* __restrict__ cv1b,
               const float* __restrict__ cv3w, const float* __restrict__ cv3b,
               const float* __restrict__ lng,  const float* __restrict__ lnb,
               const float* __restrict__ sp1w, const float* __restrict__ sp1b,
               const float* __restrict__ sp2w, const float* __restrict__ sp2b) {
    extern __shared__ float sm[];
    float* buf0 = sm;                    // TILE_F
    float* buf1 = sm + TILE_F;           // TILE_F
    float* sv   = sm + 2 * TILE_F;       // C
    float* sg   = sv + C;                // C
    float* S    = sg + C;                // C   (scalar-CTA scratch)
    float* l1   = S + C;                 // C   (scalar-CTA scratch)
    float* part = l1 + C;                // 256 (red scratch / dot partials)
    float* sy   = part + 256;            // TP
    __shared__ int swork;
    __shared__ int ssteal[3];
    __shared__ unsigned srank;

    const int t = threadIdx.x;

    // ================= Phase A: work-stolen channel sums =================
    for (;;) {
        if (t == 0) swork = atomicAdd(&d_ctrA, 1);
        __syncthreads();
        const int id = swork;
        if (id >= NCHUNKS) break;
        const int c = id >> 4, seg = id & 15;
        const float4* xc = x4 + (size_t)c * HW4 + (size_t)seg * SEG_F4;
        float s = 0.f;
#pragma unroll
        for (int j = 0; j < 16; j++) {
            float4 u = xc[t + j * 256];
            s += (u.x + u.y) + (u.z + u.w);
        }
        part[t] = s;
        __syncthreads();
        for (int off = 128; off > 0; off >>= 1) {
            if (t < off) part[t] += part[t + off];
            __syncthreads();
        }
        if (t == 0) d_partials[id] = part[0];
        __syncthreads();
    }

    // ---- phase-A completion rank ----
    __threadfence();
    if (t == 0) srank = atomicAdd(&d_doneA, 1u);
    __syncthreads();
    const bool isScalar = (srank == (unsigned)(ncta - 1));

    // ---- steal + prefetch first two phase-B tiles (overlaps stragglers/scalars) ----
    if (t == 0) {
        ssteal[0] = atomicAdd(&d_ctrB, 1);
        ssteal[1] = atomicAdd(&d_ctrB, 1);
    }
    __syncthreads();
    int cur_t = ssteal[0], nxt_t = ssteal[1];
    k3_prefetch(x4, buf0, cur_t, t);
    k3_prefetch(x4, buf1, nxt_t, t);

    // ================= Scalars (one CTA) / poll (others) =================
    if (isScalar) {
        {
            float ss = 0.f;
#pragma unroll
            for (int j = 0; j < SEGS; j++) ss += d_partials[t * SEGS + j];
            S[t] = ss;
        }
        __syncthreads();
        if (t < CH) {
            float a = 0.f;
            for (int cc = 0; cc < C; cc++) a += cv1w[t * C + cc] * S[cc];
            l1[t] = a + (float)HWn * cv1b[t];
        } else {
            const int u = t - CH;
            float a = 0.f;
            for (int cc = 0; cc < C; cc++) a += sp2w[u * C + cc] * S[cc];
            l1[t] = a * (1.f / (float)HWn) + sp2b[u];
        }
        __syncthreads();
        float zv = cv3b[t];
        for (int cc = 0; cc < CH; cc++) zv += cv3w[t * CH + cc] * l1[cc];
        part[t] = zv;
        __syncthreads();
        for (int off = 128; off > 0; off >>= 1) {
            if (t < off) part[t] += part[t + off];
            __syncthreads();
        }
        const float mu = part[0] * (1.f / (float)C);
        __syncthreads();
        part[t] = zv * zv;
        __syncthreads();
        for (int off = 128; off > 0; off >>= 1) {
            if (t < off) part[t] += part[t + off];
            __syncthreads();
        }
        const float var = part[0] * (1.f / (float)C) - mu * mu;
        __syncthreads();
        const float zn = (zv - mu) * rsqrtf(var + EPS) * lng[t] + lnb[t];
        d_g[t] = 1.f / (1.f + expf(-zn));

        part[t] = (t < CH) ? l1[CH + t] : -1e30f;
        __syncthreads();
        for (int off = 128; off > 0; off >>= 1) {
            if (t < off) part[t] = fmaxf(part[t], part[t + off]);
            __syncthreads();
        }
        const float mx = part[0];
        __syncthreads();
        part[t] = (t < CH) ? expf(l1[CH + t] - mx) : 0.f;
        __syncthreads();
        for (int off = 128; off > 0; off >>= 1) {
            if (t < off) part[t] += part[t + off];
            __syncthreads();
        }
        const float denom = part[0];
        __syncthreads();
        if (t < CH) l1[CH + t] = expf(l1[CH + t] - mx) / denom;   // wsm
        __syncthreads();
        {
            float vv = 0.f;
            for (int c_ = 0; c_ < CH; c_++) vv += l1[CH + c_] * sp1w[c_ * C + t];
            d_v[t] = vv;
        }
        if (t == 0) {
            float bb = 0.f;
            for (int c_ = 0; c_ < CH; c_++) bb += l1[CH + c_] * sp1b[c_];
            d_b0 = bb;
        }
        __threadfence();
        __syncthreads();
        if (t == 0) d_flag = 1u;    // release (plain volatile store after fence)
    } else {
        if (t == 0) {
            while (d_flag == 0u) __nanosleep(300);   // plain volatile poll, no atomics
        }
        __syncthreads();
        __threadfence();            // acquire side
    }

    sv[t] = d_v[t];
    sg[t] = d_g[t];
    const float b0 = d_b0;

    // ================= Phase B: R12-champion stealing pipeline =================
    int i = 0;
    while (cur_t < NTILES) {
        float* cur = (i & 1) ? buf1 : buf0;
        float4* cur4 = (float4*)cur;

        if (t == 0) ssteal[2] = atomicAdd(&d_ctrB, 1);
        asm volatile("cp.async.wait_group 1;\n");
        __syncthreads();
        const int nn = ssteal[2];

        {
            const int p = t & 31, q = t >> 5;
            float acc = 0.f;
            const float* tp_ = cur + (q * 32) * TP + p;
            const float* vp  = sv + q * 32;
#pragma unroll
            for (int c = 0; c < 32; c++) acc += vp[c] * tp_[c * TP];
            part[q * TP + p] = acc;
        }
        __syncthreads();
        if (t < TP) {
            float yb = b0;
#pragma unroll
            for (int q = 0; q < 8; q++) yb += part[q * TP + t];
            sy[t] = 1.f / (1.f + expf(-yb));
        }
        __syncthreads();

        const int base4 = cur_t * TP4;
#pragma unroll
        for (int j = 0; j < 8; j++) {
            int i4 = t + j * 256;
            int c = i4 >> 3, p4 = i4 & 7;
            float4 xv = cur4[i4];
            const float gv = sg[c];
            const int p = p4 * 4;
            float4 o;
            o.x = (gv + sy[p + 0]) * xv.x;
            o.y = (gv + sy[p + 1]) * xv.y;
            o.z = (gv + sy[p + 2]) * xv.z;
            o.w = (gv + sy[p + 3]) * xv.w;
            out4[(size_t)c * HW4 + base4 + p4] = o;
        }
        __syncthreads();
        k3_prefetch(x4, cur, nn, t);
        cur_t = nxt_t;
        nxt_t = nn;
        i++;
    }
    asm volatile("cp.async.wait_group 0;\n");

    // ---- epilogue: last CTA resets all coordination state for next replay ----
    __threadfence();
    if (t == 0) {
        unsigned old = atomicAdd(&d_doneB, 1u);
        if (old == (unsigned)(ncta - 1)) {
            d_ctrA = 0; d_ctrB = 0; d_doneA = 0; d_doneB = 0; d_flag = 0u;
        }
    }
}

// ---------------- Launch ----------------------------------------------------------
extern "C" void kernel_launch(void* const* d_in, const int* in_sizes, int n_in,
                              void* d_out, int out_size) {
    const float* x    = (const float*)d_in[0];
    const float* cv1w = (const float*)d_in[1];
    const float* cv1b = (const float*)d_in[2];
    // d_in[3], d_in[4] = ch_cv2_w/b : mathematically unused (softmax over size-1 dim)
    const float* cv3w = (const float*)d_in[5];
    const float* cv3b = (const float*)d_in[6];
    const float* lng  = (const float*)d_in[7];
    const float* lnb  = (const float*)d_in[8];
    const float* sp1w = (const float*)d_in[9];
    const float* sp1b = (const float*)d_in[10];
    const float* sp2w = (const float*)d_in[11];
    const float* sp2b = (const float*)d_in[12];

    int nsm = 148;
    cudaDeviceGetAttribute(&nsm, cudaDevAttrMultiProcessorCount, 0);
    const int ncta = nsm * 3;   // 3 CTAs/SM, all co-resident (poll safe)

    const int smem_bytes = (2 * TILE_F + 4 * C + 256 + TP) * (int)sizeof(float);
    cudaFuncSetAttribute(psa_fused, cudaFuncAttributeMaxDynamicSharedMemorySize, smem_bytes);
    psa_fused<<<ncta, 256, smem_bytes>>>((const float4*)x, (float4*)d_out, ncta,
                                         cv1w, cv1b, cv3w, cv3b, lng, lnb,
                                         sp1w, sp1b, sp2w, sp2b);
}

// round 15
// speedup vs baseline: 1.1165x; 1.1165x over previous
#include <cuda_runtime.h>

#define C    256
#define CH   128
#define HWn  262144
#define HW4  65536
#define SEGS 16
#define SEG_F4 4096   // HW4 / SEGS
#define EPS  1e-5f

#define TP     32
#define TP4    8
#define TILE_F  (C * TP)       // 8192 floats = 32 KB
#define NTILES  (HWn / TP)     // 8192 tiles

__device__ float d_partials[C * SEGS];
__device__ float d_g[C];
__device__ float d_v[C];
__device__ float d_b0;
__device__ unsigned d_k1done;   // reset by k1's last CTA
__device__ int d_tilectr;       // reset by k3's last CTA (k3 steals before k1 ends!)
__device__ unsigned d_k3done;   // reset by k3's last CTA

// ---------------- Kernel 1: channel sums + (last CTA) scalar algebra --------------
__global__ void k1_sums(const float4* __restrict__ x4,
                        const float* __restrict__ cv1w, const float* __restrict__ cv1b,
                        const float* __restrict__ cv3w, const float* __restrict__ cv3b,
                        const float* __restrict__ lng,  const float* __restrict__ lnb,
                        const float* __restrict__ sp1w, const float* __restrict__ sp1b,
                        const float* __restrict__ sp2w, const float* __restrict__ sp2b) {
    const int c = blockIdx.y, seg = blockIdx.x, t = threadIdx.x;
    const float4* xc = x4 + (size_t)c * HW4 + (size_t)seg * SEG_F4;
    float s = 0.f;
#pragma unroll
    for (int j = 0; j < 16; j++) {
        float4 u = xc[t + j * 256];
        s += (u.x + u.y) + (u.z + u.w);
    }
    __shared__ float red[256];
    red[t] = s;
    __syncthreads();
    for (int off = 128; off > 0; off >>= 1) {
        if (t < off) red[t] += red[t + off];
        __syncthreads();
    }
    if (t == 0) d_partials[c * SEGS + seg] = red[0];

    // allow k3's CTAs to start launching/prefetching while k1 drains
    cudaTriggerProgrammaticLaunchCompletion();

    // ---- last-CTA detection ----
    __shared__ unsigned slast;
    if (t == 0) {
        __threadfence();
        unsigned old = atomicAdd(&d_k1done, 1u);
        slast = (old == (unsigned)(SEGS * C - 1)) ? 1u : 0u;
        if (slast) __threadfence();
    }
    __syncthreads();
    if (!slast) return;

    if (t == 0) d_k1done = 0u;   // reset for next replay

    __shared__ float S[C];
    __shared__ float l1[C];     // ybuf in [0,CH), s2pre/wsm in [CH,2CH)
    {
        float ss = 0.f;
#pragma unroll
        for (int j = 0; j < SEGS; j++) ss += d_partials[t * SEGS + j];
        S[t] = ss;
    }
    __syncthreads();

    if (t < CH) {
        float a = 0.f;
        for (int cc = 0; cc < C; cc++) a += cv1w[t * C + cc] * S[cc];
        l1[t] = a + (float)HWn * cv1b[t];
    } else {
        const int u = t - CH;
        float a = 0.f;
        for (int cc = 0; cc < C; cc++) a += sp2w[u * C + cc] * S[cc];
        l1[t] = a * (1.f / (float)HWn) + sp2b[u];
    }
    __syncthreads();

    float zv = cv3b[t];
    for (int cc = 0; cc < CH; cc++) zv += cv3w[t * CH + cc] * l1[cc];

    red[t] = zv;
    __syncthreads();
    for (int off = 128; off > 0; off >>= 1) {
        if (t < off) red[t] += red[t + off];
        __syncthreads();
    }
    const float mu = red[0] * (1.f / (float)C);
    __syncthreads();
    red[t] = zv * zv;
    __syncthreads();
    for (int off = 128; off > 0; off >>= 1) {
        if (t < off) red[t] += red[t + off];
        __syncthreads();
    }
    const float var = red[0] * (1.f / (float)C) - mu * mu;
    __syncthreads();

    const float zn = (zv - mu) * rsqrtf(var + EPS) * lng[t] + lnb[t];
    d_g[t] = 1.f / (1.f + expf(-zn));

    red[t] = (t < CH) ? l1[CH + t] : -1e30f;
    __syncthreads();
    for (int off = 128; off > 0; off >>= 1) {
        if (t < off) red[t] = fmaxf(red[t], red[t + off]);
        __syncthreads();
    }
    const float mx = red[0];
    __syncthreads();
    red[t] = (t < CH) ? expf(l1[CH + t] - mx) : 0.f;
    __syncthreads();
    for (int off = 128; off > 0; off >>= 1) {
        if (t < off) red[t] += red[t + off];
        __syncthreads();
    }
    const float denom = red[0];
    __syncthreads();
    if (t < CH) l1[CH + t] = expf(l1[CH + t] - mx) / denom;   // wsm
    __syncthreads();

    {
        float vv = 0.f;
        for (int c_ = 0; c_ < CH; c_++) vv += l1[CH + c_] * sp1w[c_ * C + t];
        d_v[t] = vv;
    }
    if (t == 0) {
        float bb = 0.f;
        for (int c_ = 0; c_ < CH; c_++) bb += l1[CH + c_] * sp1b[c_];
        d_b0 = bb;
    }
}

// ---------------- Kernel 3: PDL-overlapped work-stealing pipeline ----------------
__device__ __forceinline__ void k3_prefetch(const float4* __restrict__ x4,
                                            float* buf, int tile, int t) {
    if (tile < NTILES) {
        unsigned dst_base = (unsigned)__cvta_generic_to_shared(buf);
        const int base4 = tile * TP4;
#pragma unroll
        for (int j = 0; j < 8; j++) {
            int i4 = t + j * 256;
            int c = i4 >> 3, p4 = i4 & 7;
            const float4* src = x4 + (size_t)c * HW4 + base4 + p4;
            unsigned dst = dst_base + i4 * 16;
            asm volatile("cp.async.cg.shared.global [%0], [%1], 16;\n" :: "r"(dst), "l"(src));
        }
    }
    asm volatile("cp.async.commit_group;\n");
}

__global__ __launch_bounds__(256, 3)
void k3_out(const float4* __restrict__ x4, float4* __restrict__ out4, int ncta) {
    extern __shared__ float sm[];
    float* buf0 = sm;                    // TILE_F
    float* buf1 = sm + TILE_F;           // TILE_F
    float* sv   = sm + 2 * TILE_F;       // C
    float* sg   = sv + C;                // C
    float* part = sg + C;                // 256
    float* sy   = part + 256;            // TP
    __shared__ int ssteal[3];

    const int t = threadIdx.x;

    // ---- preamble: steal + prefetch BEFORE waiting on k1 (x is read-only) ----
    if (t == 0) {
        ssteal[0] = atomicAdd(&d_tilectr, 1);
        ssteal[1] = atomicAdd(&d_tilectr, 1);
    }
    __syncthreads();
    int cur_t = ssteal[0], nxt_t = ssteal[1];
    k3_prefetch(x4, buf0, cur_t, t);
    k3_prefetch(x4, buf1, nxt_t, t);

    // ---- wait for k1 grid (scalars) to be fully visible ----
    cudaGridDependencySynchronize();

    sv[t] = d_v[t];
    sg[t] = d_g[t];
    const float b0 = d_b0;

    int i = 0;
    while (cur_t < NTILES) {
        float* cur = (i & 1) ? buf1 : buf0;
        float4* cur4 = (float4*)cur;

        if (t == 0) ssteal[2] = atomicAdd(&d_tilectr, 1);   // latency hidden by wait
        asm volatile("cp.async.wait_group 1;\n");           // current tile landed
        __syncthreads();                                    // publishes ssteal[2] too
        const int nn = ssteal[2];

        // yb partial dots: p = pixel (0..31), q = channel octant (0..7)
        {
            const int p = t & 31, q = t >> 5;
            float acc = 0.f;
            const float* tp_ = cur + (q * 32) * TP + p;
            const float* vp  = sv + q * 32;
#pragma unroll
            for (int c = 0; c < 32; c++) acc += vp[c] * tp_[c * TP];
            part[q * TP + p] = acc;
        }
        __syncthreads();
        if (t < TP) {
            float yb = b0;
#pragma unroll
            for (int q = 0; q < 8; q++) yb += part[q * TP + t];
            sy[t] = 1.f / (1.f + expf(-yb));
        }
        __syncthreads();

        // out = (g[c] + sigmoid(yb[p])) * x
        const int base4 = cur_t * TP4;
#pragma unroll
        for (int j = 0; j < 8; j++) {
            int i4 = t + j * 256;
            int c = i4 >> 3, p4 = i4 & 7;
            float4 xv = cur4[i4];
            const float gv = sg[c];
            const int p = p4 * 4;
            float4 o;
            o.x = (gv + sy[p + 0]) * xv.x;
            o.y = (gv + sy[p + 1]) * xv.y;
            o.z = (gv + sy[p + 2]) * xv.z;
            o.w = (gv + sy[p + 3]) * xv.w;
            out4[(size_t)c * HW4 + base4 + p4] = o;
        }
        __syncthreads();                 // cur consumed
        k3_prefetch(x4, cur, nn, t);     // refill cur with stolen tile
        cur_t = nxt_t;
        nxt_t = nn;
        i++;
    }
    asm volatile("cp.async.wait_group 0;\n");   // drain before exit

    // ---- epilogue: last k3 CTA resets stealing state for next replay ----
    __threadfence();
    if (t == 0) {
        unsigned old = atomicAdd(&d_k3done, 1u);
        if (old == (unsigned)(ncta - 1)) {
            d_tilectr = 0;
            d_k3done = 0u;
        }
    }
}

// ---------------- Launch ----------------------------------------------------------
extern "C" void kernel_launch(void* const* d_in, const int* in_sizes, int n_in,
                              void* d_out, int out_size) {
    const float* x    = (const float*)d_in[0];
    const float* cv1w = (const float*)d_in[1];
    const float* cv1b = (const float*)d_in[2];
    // d_in[3], d_in[4] = ch_cv2_w/b : mathematically unused (softmax over size-1 dim)
    const float* cv3w = (const float*)d_in[5];
    const float* cv3b = (const float*)d_in[6];
    const float* lng  = (const float*)d_in[7];
    const float* lnb  = (const float*)d_in[8];
    const float* sp1w = (const float*)d_in[9];
    const float* sp1b = (const float*)d_in[10];
    const float* sp2w = (const float*)d_in[11];
    const float* sp2b = (const float*)d_in[12];

    int nsm = 148;
    cudaDeviceGetAttribute(&nsm, cudaDevAttrMultiProcessorCount, 0);
    const int ncta = nsm * 3;   // 3 CTAs/SM

    dim3 g1(SEGS, C);
    k1_sums<<<g1, 256>>>((const float4*)x, cv1w, cv1b, cv3w, cv3b, lng, lnb,
                         sp1w, sp1b, sp2w, sp2b);

    const int smem_bytes = (2 * TILE_F + C + C + 256 + TP) * (int)sizeof(float);
    cudaFuncSetAttribute(k3_out, cudaFuncAttributeMaxDynamicSharedMemorySize, smem_bytes);

    // PDL launch: k3 may begin (prefetch phase) while k1 drains
    cudaLaunchConfig_t cfg = {};
    cfg.gridDim = dim3(ncta, 1, 1);
    cfg.blockDim = dim3(256, 1, 1);
    cfg.dynamicSmemBytes = smem_bytes;
    cfg.stream = 0;
    cudaLaunchAttribute attrs[1];
    attrs[0].id = cudaLaunchAttributeProgrammaticStreamSerialization;
    attrs[0].val.programmaticStreamSerializationAllowed = 1;
    cfg.attrs = attrs;
    cfg.numAttrs = 1;
    cudaLaunchKernelEx(&cfg, k3_out, (const float4*)x, (float4*)d_out, ncta);
}